// round 8
// baseline (speedup 1.0000x reference)
#include <cuda_runtime.h>
#include <cuda_bf16.h>
#include <cstdint>

// Problem constants
#define BATCH 64
#define TSTEPS 2048
#define DIN 128
#define HID 256
#define DOUT 128
#define G4H (4*HID)        // 1024

// Scan tiling: 32 column-groups x 4 bg-pairs = 128 CTAs, 2 batch-groups per CTA
#define NCTA 128
#define NCG 32             // column groups
#define JPC 8              // hidden units per CTA
#define NCOL 32            // gate columns per CTA (4 gates x 8)
#define BPC 8              // batches per group
#define KC 32              // K per warp (8 warps)
#define NTHREADS 256

// SMEM (floats)
#define SWSTR 34                          // sW2 [k][c] staging stride
#define PSTR 36                           // sPart row stride
#define SM_SW2   0                        // 256*34 = 8704 (setup only)
#define SM_H     (SM_SW2 + 256*SWSTR)     // sH [k(256)][b(8)] = 2048
#define SM_PART  (SM_H + 256*8)           // 2 phases x 64 x PSTR = 4608
#define SM_C     (SM_PART + 2*64*PSTR)    // 128 (A:0-63, B:64-127)
#define SM_FLOATS (SM_C + 128)
#define SMEM_BYTES (SM_FLOATS*4)          // ~62 KB

// x_proj kernel smem
#define XP_XSTRIDE 133
#define XP_WSTRIDE 132
#define XPK_SX    0
#define XPK_SW    (128*XP_XSTRIDE)
#define XPK_FLOATS (XPK_SW + 128*XP_WSTRIDE)
#define XPK_BYTES (XPK_FLOATS*4)

// Global scratch
__device__ __align__(16) float g_xp[(size_t)TSTEPS * NCG * 8 * 256]; // [t][cg][bg][bb*32+c]
__device__ __align__(16) float g_h[2][8][NCG][JPC*BPC];              // [buf][bg][cg][lj*8+bb]
__device__ unsigned g_flags[8][NCG][32];                             // [bg][cg], 128B apart

__device__ __forceinline__ uint32_t smem_u32(const void* p) {
    return (uint32_t)__cvta_generic_to_shared(p);
}
__device__ __forceinline__ float fast_sig(float x) {
    return __fdividef(1.0f, 1.0f + __expf(-x));
}
__device__ __forceinline__ float fast_tanh(float x) {
    return __fdividef(2.0f, 1.0f + __expf(-2.0f * x)) - 1.0f;
}

// ---------------------------------------------------------------------------
__global__ void init_kernel() {
    int i = blockIdx.x * blockDim.x + threadIdx.x;
    if (i < 8 * NCG * 32) ((unsigned*)g_flags)[i] = 0u;
    if (i < 8 * NCG * JPC * BPC) ((float*)g_h[0])[i] = 0.0f;
}

// ---------------------------------------------------------------------------
// x_proj: g_xp[t][cg][bg][bb*32 + gate*8+lj] = x[b,t,:] . W_x[:, gcol] + bias
// ---------------------------------------------------------------------------
__global__ void __launch_bounds__(NTHREADS, 1)
xproj_kernel(const float* __restrict__ x,
             const float* __restrict__ W_x,
             const float* __restrict__ bias) {
    extern __shared__ float smem[];
    float* sX = smem + XPK_SX;
    float* sW = smem + XPK_SW;

    const int tid  = threadIdx.x;
    const int tblk = blockIdx.x;
    const int bg   = blockIdx.y;

    for (int idx = tid; idx < 128 * 32; idx += NTHREADS) {
        int r = idx >> 5, f4 = idx & 31;
        int tt = r >> 3, bb = r & 7;
        int b = bg * 8 + bb, t = tblk * 16 + tt;
        float4 v = __ldg(reinterpret_cast<const float4*>(
            x + ((size_t)b * TSTEPS + t) * DIN) + f4);
        float* dst = sX + r * XP_XSTRIDE + f4 * 4;
        dst[0] = v.x; dst[1] = v.y; dst[2] = v.z; dst[3] = v.w;
    }

    const int cq = tid & 7;
    const int rg = tid >> 3;

    for (int p = 0; p < 8; p++) {
        const int cp0 = p * 128;
        __syncthreads();
        for (int idx = tid; idx < 128 * 32; idx += NTHREADS) {
            int d = idx >> 5, c4 = idx & 31;
            float4 v = __ldg(reinterpret_cast<const float4*>(
                W_x + (size_t)d * G4H + cp0) + c4);
            float* dst = sW + d * XP_WSTRIDE + c4 * 4;
            dst[0] = v.x; dst[1] = v.y; dst[2] = v.z; dst[3] = v.w;
        }
        __syncthreads();

        unsigned long long acc[4][8];
        #pragma unroll
        for (int qq = 0; qq < 8; qq++) {
            float2 bv = __ldg(reinterpret_cast<const float2*>(
                bias + cp0 + 2 * (cq + 8 * qq)));
            unsigned long long bu;
            asm("mov.b64 %0, {%1, %2};" : "=l"(bu) : "f"(bv.x), "f"(bv.y));
            #pragma unroll
            for (int rr = 0; rr < 4; rr++) acc[rr][qq] = bu;
        }

        #pragma unroll 4
        for (int d = 0; d < 128; d++) {
            unsigned long long x2[4];
            #pragma unroll
            for (int rr = 0; rr < 4; rr++) {
                float xv = sX[(rg * 4 + rr) * XP_XSTRIDE + d];
                asm("mov.b64 %0, {%1, %1};" : "=l"(x2[rr]) : "f"(xv));
            }
            const uint32_t wrow = smem_u32(sW + d * XP_WSTRIDE + 2 * cq);
            #pragma unroll
            for (int qq = 0; qq < 8; qq++) {
                unsigned long long w2;
                asm volatile("ld.shared.u64 %0, [%1];"
                             : "=l"(w2) : "r"(wrow + qq * 64));
                #pragma unroll
                for (int rr = 0; rr < 4; rr++)
                    asm volatile("fma.rn.f32x2 %0, %1, %2, %0;"
                                 : "+l"(acc[rr][qq]) : "l"(x2[rr]), "l"(w2));
            }
        }

        #pragma unroll
        for (int rr = 0; rr < 4; rr++) {
            int r = rg * 4 + rr;
            int tt = r >> 3, bb = r & 7;
            int t = tblk * 16 + tt;
            #pragma unroll
            for (int qq = 0; qq < 8; qq++) {
                int cglob = cp0 + 2 * (cq + 8 * qq);
                int gate = cglob >> 8, j = cglob & 255;
                int cg = j >> 3, lj = j & 7;
                float lo, hi;
                asm("mov.b64 {%0,%1}, %2;" : "=f"(lo), "=f"(hi) : "l"(acc[rr][qq]));
                float2* dst = reinterpret_cast<float2*>(
                    g_xp + ((size_t)((t * NCG + cg) * 8 + bg)) * 256
                         + bb * 32 + gate * 8 + lj);
                *dst = make_float2(lo, hi);
            }
        }
    }
}

// ---------------------------------------------------------------------------
// persistent LSTM scan: 2 batch-groups per CTA, alternating phases.
// W_h slice in registers; per-warp flag waits; epilogue A by warps 0-1,
// epilogue B by warps 2-3.
// ---------------------------------------------------------------------------
__global__ void __launch_bounds__(NTHREADS, 1)
lstm_scan_kernel(const float* __restrict__ W_h) {
    extern __shared__ float smem[];
    float* sW2   = smem + SM_SW2;   // [k][c] staging (setup only)
    float* sH    = smem + SM_H;     // [k(256)][b(8)]  (warp-private rows)
    float* sPart = smem + SM_PART;  // [phase][w*8+b][c] stride PSTR
    float* sC    = smem + SM_C;     // A: 0-63, B: 64-127

    const int tid = threadIdx.x;
    const int cg  = blockIdx.x & (NCG - 1);
    const int pr  = blockIdx.x >> 5;          // bg pair 0..3
    const int bgA = 2 * pr, bgB = 2 * pr + 1;
    const int j0  = cg * JPC;

    // ---- stage W_h slice as [k][c], c = gate*8+lj
    for (int idx = tid; idx < 256 * NCOL; idx += NTHREADS) {
        int k = idx >> 5, c = idx & 31;
        int gate = c >> 3, lj = c & 7;
        sW2[k * SWSTR + c] = W_h[(size_t)k * G4H + gate * HID + j0 + lj];
    }
    if (tid < 128) sC[tid] = 0.0f;
    __syncthreads();

    const int w    = tid >> 5;            // warp = k-chunk
    const int lane = tid & 31;
    const int bq   = lane >> 3;           // batch pair: batches 2bq, 2bq+1
    const int lc   = lane & 7;            // owns cols 4lc..4lc+3
    const int k0   = w * KC;

    unsigned long long wreg[2][KC];       // [col pair][k]
    {
        const uint32_t wb = smem_u32(sW2 + k0 * SWSTR + 4 * lc);
        #pragma unroll
        for (int k = 0; k < KC; k++) {
            asm volatile("ld.shared.u64 %0, [%1];"
                         : "=l"(wreg[0][k]) : "r"(wb + k * (SWSTR * 4)));
            asm volatile("ld.shared.u64 %0, [%1];"
                         : "=l"(wreg[1][k]) : "r"(wb + k * (SWSTR * 4) + 8));
        }
    }
    __syncthreads();   // sW2 dead

    const uint32_t hbase  = smem_u32(sH + k0 * BPC + 2 * bq);
    const uint32_t hstore = smem_u32(sH + k0 * BPC) + lane * 16;

    // epilogue decode
    const bool epiA = (tid < 64);
    const bool epiB = (tid >= 64 && tid < 128);
    const int  et   = tid & 63;
    const int  lj   = et >> 3;
    const int  bb   = et & 7;

    for (int s = 0; s < TSTEPS; s++) {
        const int rbuf = s & 1;
        const int nbuf = rbuf ^ 1;

        // ================= PHASE A (bgA) =================
        {
            float* sP = sPart + 0 * (64 * PSTR);

            float xr[4];
            if (epiA) {
                const float* xpb = g_xp
                    + ((size_t)((s * NCG + cg) * 8 + bgA)) * 256 + bb * 32 + lj;
                #pragma unroll
                for (int g = 0; g < 4; g++) xr[g] = __ldg(xpb + g * 8);
            }

            if (s > 0) {
                if (lane < 4) {
                    unsigned* f = &g_flags[bgA][4 * w + lane][0];
                    unsigned v;
                    do {
                        asm volatile("ld.acquire.gpu.global.u32 %0, [%1];"
                                     : "=r"(v) : "l"(f) : "memory");
                    } while (v < (unsigned)s);
                }
                __syncwarp();
            }
            {   // pull 1KB: blocks 4w..4w+3 are contiguous
                const float4* src = reinterpret_cast<const float4*>(
                    g_h[rbuf][bgA][4 * w]);
                float4 v0 = __ldcg(src + lane);
                float4 v1 = __ldcg(src + 32 + lane);
                asm volatile("st.shared.v4.f32 [%0], {%1,%2,%3,%4};"
                             :: "r"(hstore), "f"(v0.x), "f"(v0.y), "f"(v0.z), "f"(v0.w));
                asm volatile("st.shared.v4.f32 [%0], {%1,%2,%3,%4};"
                             :: "r"(hstore + 512), "f"(v1.x), "f"(v1.y), "f"(v1.z), "f"(v1.w));
            }
            __syncwarp();

            unsigned long long acc00 = 0ull, acc01 = 0ull, acc10 = 0ull, acc11 = 0ull;
            #pragma unroll
            for (int k = 0; k < KC; k++) {
                float h0, h1;
                asm volatile("ld.shared.v2.f32 {%0,%1}, [%2];"
                             : "=f"(h0), "=f"(h1) : "r"(hbase + k * 32));
                unsigned long long hh0, hh1;
                asm("mov.b64 %0, {%1, %1};" : "=l"(hh0) : "f"(h0));
                asm("mov.b64 %0, {%1, %1};" : "=l"(hh1) : "f"(h1));
                asm volatile("fma.rn.f32x2 %0, %1, %2, %0;"
                             : "+l"(acc00) : "l"(hh0), "l"(wreg[0][k]));
                asm volatile("fma.rn.f32x2 %0, %1, %2, %0;"
                             : "+l"(acc01) : "l"(hh0), "l"(wreg[1][k]));
                asm volatile("fma.rn.f32x2 %0, %1, %2, %0;"
                             : "+l"(acc10) : "l"(hh1), "l"(wreg[0][k]));
                asm volatile("fma.rn.f32x2 %0, %1, %2, %0;"
                             : "+l"(acc11) : "l"(hh1), "l"(wreg[1][k]));
            }
            {
                int row0 = (w * BPC + 2 * bq) * PSTR + 4 * lc;
                *reinterpret_cast<unsigned long long*>(sP + row0)            = acc00;
                *reinterpret_cast<unsigned long long*>(sP + row0 + 2)        = acc01;
                *reinterpret_cast<unsigned long long*>(sP + row0 + PSTR)     = acc10;
                *reinterpret_cast<unsigned long long*>(sP + row0 + PSTR + 2) = acc11;
            }
            __syncthreads();

            if (epiA) {
                float g4[4];
                #pragma unroll
                for (int g = 0; g < 4; g++) {
                    float v = xr[g];
                    #pragma unroll
                    for (int q = 0; q < 8; q++)
                        v += sP[(q * BPC + bb) * PSTR + g * 8 + lj];
                    g4[g] = v;
                }
                float ig = fast_sig(g4[0]);
                float fg = fast_sig(g4[1]);
                float gg = fast_tanh(g4[2]);
                float og = fast_sig(g4[3]);
                float cnew = fg * sC[tid] + ig * gg;
                sC[tid] = cnew;
                float hnew = og * fast_tanh(cnew);
                __stcg(&g_h[nbuf][bgA][cg][et], hnew);   // 256B coalesced
                asm volatile("bar.sync 1, 64;" ::: "memory");
                if (tid == 0)
                    asm volatile("st.release.gpu.global.u32 [%0], %1;"
                                 :: "l"(&g_flags[bgA][cg][0]),
                                    "r"((unsigned)(s + 1)) : "memory");
            }
        }

        // ================= PHASE B (bgB) =================
        {
            float* sP = sPart + 1 * (64 * PSTR);

            float xr[4];
            if (epiB) {
                const float* xpb = g_xp
                    + ((size_t)((s * NCG + cg) * 8 + bgB)) * 256 + bb * 32 + lj;
                #pragma unroll
                for (int g = 0; g < 4; g++) xr[g] = __ldg(xpb + g * 8);
            }

            if (s > 0) {
                if (lane < 4) {
                    unsigned* f = &g_flags[bgB][4 * w + lane][0];
                    unsigned v;
                    do {
                        asm volatile("ld.acquire.gpu.global.u32 %0, [%1];"
                                     : "=r"(v) : "l"(f) : "memory");
                    } while (v < (unsigned)s);
                }
                __syncwarp();
            }
            {
                const float4* src = reinterpret_cast<const float4*>(
                    g_h[rbuf][bgB][4 * w]);
                float4 v0 = __ldcg(src + lane);
                float4 v1 = __ldcg(src + 32 + lane);
                asm volatile("st.shared.v4.f32 [%0], {%1,%2,%3,%4};"
                             :: "r"(hstore), "f"(v0.x), "f"(v0.y), "f"(v0.z), "f"(v0.w));
                asm volatile("st.shared.v4.f32 [%0], {%1,%2,%3,%4};"
                             :: "r"(hstore + 512), "f"(v1.x), "f"(v1.y), "f"(v1.z), "f"(v1.w));
            }
            __syncwarp();

            unsigned long long acc00 = 0ull, acc01 = 0ull, acc10 = 0ull, acc11 = 0ull;
            #pragma unroll
            for (int k = 0; k < KC; k++) {
                float h0, h1;
                asm volatile("ld.shared.v2.f32 {%0,%1}, [%2];"
                             : "=f"(h0), "=f"(h1) : "r"(hbase + k * 32));
                unsigned long long hh0, hh1;
                asm("mov.b64 %0, {%1, %1};" : "=l"(hh0) : "f"(h0));
                asm("mov.b64 %0, {%1, %1};" : "=l"(hh1) : "f"(h1));
                asm volatile("fma.rn.f32x2 %0, %1, %2, %0;"
                             : "+l"(acc00) : "l"(hh0), "l"(wreg[0][k]));
                asm volatile("fma.rn.f32x2 %0, %1, %2, %0;"
                             : "+l"(acc01) : "l"(hh0), "l"(wreg[1][k]));
                asm volatile("fma.rn.f32x2 %0, %1, %2, %0;"
                             : "+l"(acc10) : "l"(hh1), "l"(wreg[0][k]));
                asm volatile("fma.rn.f32x2 %0, %1, %2, %0;"
                             : "+l"(acc11) : "l"(hh1), "l"(wreg[1][k]));
            }
            {
                int row0 = (w * BPC + 2 * bq) * PSTR + 4 * lc;
                *reinterpret_cast<unsigned long long*>(sP + row0)            = acc00;
                *reinterpret_cast<unsigned long long*>(sP + row0 + 2)        = acc01;
                *reinterpret_cast<unsigned long long*>(sP + row0 + PSTR)     = acc10;
                *reinterpret_cast<unsigned long long*>(sP + row0 + PSTR + 2) = acc11;
            }
            __syncthreads();

            if (epiB) {
                float g4[4];
                #pragma unroll
                for (int g = 0; g < 4; g++) {
                    float v = xr[g];
                    #pragma unroll
                    for (int q = 0; q < 8; q++)
                        v += sP[(q * BPC + bb) * PSTR + g * 8 + lj];
                    g4[g] = v;
                }
                float ig = fast_sig(g4[0]);
                float fg = fast_sig(g4[1]);
                float gg = fast_tanh(g4[2]);
                float og = fast_sig(g4[3]);
                float cnew = fg * sC[tid] + ig * gg;
                sC[tid] = cnew;
                float hnew = og * fast_tanh(cnew);
                __stcg(&g_h[nbuf][bgB][cg][et], hnew);
                asm volatile("bar.sync 2, 64;" ::: "memory");
                if (tid == 64)
                    asm volatile("st.release.gpu.global.u32 [%0], %1;"
                                 :: "l"(&g_flags[bgB][cg][0]),
                                    "r"((unsigned)(s + 1)) : "memory");
            }
        }
    }
}

// ---------------------------------------------------------------------------
// final FC: out[b][d] = sum_k h_final[k][b] * fc_w[k][d] + fc_b[d]
// h_2048 lives in g_h[0][bg][k>>3][(k&7)*8+bb]
// ---------------------------------------------------------------------------
__global__ void fc_kernel(const float* __restrict__ fc_w,
                          const float* __restrict__ fc_b,
                          float* __restrict__ out) {
    int b = blockIdx.x;
    int d = threadIdx.x;
    int bg = b >> 3, bb = b & 7;
    float acc = fc_b[d];
    #pragma unroll 8
    for (int k = 0; k < HID; k++)
        acc += g_h[0][bg][k >> 3][(k & 7) * 8 + bb] * fc_w[k * DOUT + d];
    out[b * DOUT + d] = acc;
}

// ---------------------------------------------------------------------------
extern "C" void kernel_launch(void* const* d_in, const int* in_sizes, int n_in,
                              void* d_out, int out_size) {
    const float* x    = (const float*)d_in[0];
    const float* W_x  = (const float*)d_in[1];
    const float* W_h  = (const float*)d_in[2];
    const float* bvec = (const float*)d_in[3];
    const float* fc_w = (const float*)d_in[4];
    const float* fc_b = (const float*)d_in[5];
    float* out = (float*)d_out;

    cudaFuncSetAttribute(xproj_kernel,
                         cudaFuncAttributeMaxDynamicSharedMemorySize, XPK_BYTES);
    cudaFuncSetAttribute(lstm_scan_kernel,
                         cudaFuncAttributeMaxDynamicSharedMemorySize, SMEM_BYTES);

    init_kernel<<<(8 * NCG * 32 + 255) / 256, 256>>>();
    xproj_kernel<<<dim3(TSTEPS / 16, 8), NTHREADS, XPK_BYTES>>>(x, W_x, bvec);
    lstm_scan_kernel<<<NCTA, NTHREADS, SMEM_BYTES>>>(W_h);
    fc_kernel<<<BATCH, DOUT>>>(fc_w, fc_b, out);
}

// round 9
// speedup vs baseline: 1.3894x; 1.3894x over previous
#include <cuda_runtime.h>
#include <cuda_bf16.h>
#include <cstdint>

// Problem constants
#define BATCH 64
#define TSTEPS 2048
#define DIN 128
#define HID 256
#define DOUT 128
#define G4H (4*HID)        // 1024

// Scan tiling: 16 column-groups x 8 batch-groups = 128 CTAs
#define NCTA 128
#define JPC 16             // hidden units per CTA
#define NCOL 64            // gate columns per CTA
#define BPC 8              // batches per CTA
#define KC 32              // K per warp (8 warps)
#define NTHREADS 256

// SMEM (floats)
#define SWSTR 66                         // sW2 [k][c] staging stride
#define PSTR 70                          // sPart row stride
#define SM_SW2   0                       // 256*66 = 16896 (setup only)
#define SM_H     (SM_SW2 + 256*SWSTR)    // sH [k(256)][b(8)] = 2048
#define SM_PART  (SM_H + 256*8)          // 2 x 8 x 8 x PSTR = 8960
#define SM_C     (SM_PART + 2*8*8*PSTR)  // 128
#define SM_FLOATS (SM_C + 128)
#define SMEM_BYTES (SM_FLOATS*4)         // ~113 KB

// x_proj kernel smem
#define XP_XSTRIDE 133
#define XP_WSTRIDE 132
#define XPK_SX    0
#define XPK_SW    (128*XP_XSTRIDE)
#define XPK_FLOATS (XPK_SW + 128*XP_WSTRIDE)
#define XPK_BYTES (XPK_FLOATS*4)

// Global scratch
__device__ __align__(16) float g_xp[(size_t)TSTEPS * 16 * 8 * 512];      // [t][cg][bg][bb*64+c]
// tagged h words: {hi32 = step tag, lo32 = h bits}; [buf][bg][cg][lj*8+bb]
__device__ __align__(16) unsigned long long g_hx[2][8][16][JPC*BPC];

__device__ __forceinline__ uint32_t smem_u32(const void* p) {
    return (uint32_t)__cvta_generic_to_shared(p);
}
__device__ __forceinline__ float fast_sig(float x) {
    return __fdividef(1.0f, 1.0f + __expf(-x));
}
__device__ __forceinline__ float fast_tanh(float x) {
    return __fdividef(2.0f, 1.0f + __expf(-2.0f * x)) - 1.0f;
}
__device__ __forceinline__ unsigned long long ld_relaxed_u64(
        const unsigned long long* p) {
    unsigned long long v;
    asm volatile("ld.relaxed.gpu.global.u64 %0, [%1];"
                 : "=l"(v) : "l"(p) : "memory");
    return v;
}

// ---------------------------------------------------------------------------
__global__ void init_kernel() {
    int i = blockIdx.x * blockDim.x + threadIdx.x;
    int total = 2 * 8 * 16 * JPC * BPC;
    if (i < total) ((unsigned long long*)g_hx)[i] = 0ull;  // tag 0, h = 0
}

// ---------------------------------------------------------------------------
// x_proj: g_xp[t][cg][bg][bb*64 + gate*16+lj] = x[b,t,:] . W_x[:, gcol] + bias
// ---------------------------------------------------------------------------
__global__ void __launch_bounds__(NTHREADS, 1)
xproj_kernel(const float* __restrict__ x,
             const float* __restrict__ W_x,
             const float* __restrict__ bias) {
    extern __shared__ float smem[];
    float* sX = smem + XPK_SX;
    float* sW = smem + XPK_SW;

    const int tid  = threadIdx.x;
    const int tblk = blockIdx.x;
    const int bg   = blockIdx.y;

    for (int idx = tid; idx < 128 * 32; idx += NTHREADS) {
        int r = idx >> 5, f4 = idx & 31;
        int tt = r >> 3, bb = r & 7;
        int b = bg * 8 + bb, t = tblk * 16 + tt;
        float4 v = __ldg(reinterpret_cast<const float4*>(
            x + ((size_t)b * TSTEPS + t) * DIN) + f4);
        float* dst = sX + r * XP_XSTRIDE + f4 * 4;
        dst[0] = v.x; dst[1] = v.y; dst[2] = v.z; dst[3] = v.w;
    }

    const int cq = tid & 7;
    const int rg = tid >> 3;

    for (int p = 0; p < 8; p++) {
        const int cp0 = p * 128;
        __syncthreads();
        for (int idx = tid; idx < 128 * 32; idx += NTHREADS) {
            int d = idx >> 5, c4 = idx & 31;
            float4 v = __ldg(reinterpret_cast<const float4*>(
                W_x + (size_t)d * G4H + cp0) + c4);
            float* dst = sW + d * XP_WSTRIDE + c4 * 4;
            dst[0] = v.x; dst[1] = v.y; dst[2] = v.z; dst[3] = v.w;
        }
        __syncthreads();

        unsigned long long acc[4][8];
        #pragma unroll
        for (int qq = 0; qq < 8; qq++) {
            float2 bv = __ldg(reinterpret_cast<const float2*>(
                bias + cp0 + 2 * (cq + 8 * qq)));
            unsigned long long bu;
            asm("mov.b64 %0, {%1, %2};" : "=l"(bu) : "f"(bv.x), "f"(bv.y));
            #pragma unroll
            for (int rr = 0; rr < 4; rr++) acc[rr][qq] = bu;
        }

        #pragma unroll 4
        for (int d = 0; d < 128; d++) {
            unsigned long long x2[4];
            #pragma unroll
            for (int rr = 0; rr < 4; rr++) {
                float xv = sX[(rg * 4 + rr) * XP_XSTRIDE + d];
                asm("mov.b64 %0, {%1, %1};" : "=l"(x2[rr]) : "f"(xv));
            }
            const uint32_t wrow = smem_u32(sW + d * XP_WSTRIDE + 2 * cq);
            #pragma unroll
            for (int qq = 0; qq < 8; qq++) {
                unsigned long long w2;
                asm volatile("ld.shared.u64 %0, [%1];"
                             : "=l"(w2) : "r"(wrow + qq * 64));
                #pragma unroll
                for (int rr = 0; rr < 4; rr++)
                    asm volatile("fma.rn.f32x2 %0, %1, %2, %0;"
                                 : "+l"(acc[rr][qq]) : "l"(x2[rr]), "l"(w2));
            }
        }

        #pragma unroll
        for (int rr = 0; rr < 4; rr++) {
            int r = rg * 4 + rr;
            int tt = r >> 3, bb = r & 7;
            int t = tblk * 16 + tt;
            #pragma unroll
            for (int qq = 0; qq < 8; qq++) {
                int cglob = cp0 + 2 * (cq + 8 * qq);
                int gate = cglob >> 8, rem = cglob & 255;
                int cg = rem >> 4, lj = rem & 15;
                float lo, hi;
                asm("mov.b64 {%0,%1}, %2;" : "=f"(lo), "=f"(hi) : "l"(acc[rr][qq]));
                float2* dst = reinterpret_cast<float2*>(
                    g_xp + ((size_t)((t * 16 + cg) * 8 + bg)) * 512
                         + bb * 64 + gate * 16 + lj);
                *dst = make_float2(lo, hi);
            }
        }
    }
}

// ---------------------------------------------------------------------------
// persistent LSTM scan: W_h in registers; self-tagging h words (1-hop sync)
// ---------------------------------------------------------------------------
__global__ void __launch_bounds__(NTHREADS, 1)
lstm_scan_kernel(const float* __restrict__ W_h) {
    extern __shared__ float smem[];
    float* sW2   = smem + SM_SW2;   // [k][c] staging (setup only)
    float* sH    = smem + SM_H;     // [k(256)][b(8)]
    float* sPart = smem + SM_PART;  // [buf][w][b][c] stride PSTR
    float* sC    = smem + SM_C;     // [lj*8+bb]

    const int tid = threadIdx.x;
    const int cg  = blockIdx.x & 15;
    const int bg  = blockIdx.x >> 4;
    const int j0  = cg * JPC;

    // ---- stage W_h slice as [k][c] then load into registers
    for (int idx = tid; idx < KC * 8 * NCOL; idx += NTHREADS) {
        int k = idx >> 6, c = idx & 63;
        int gate = c >> 4, lj = c & 15;
        sW2[k * SWSTR + c] = W_h[(size_t)k * G4H + gate * HID + j0 + lj];
    }
    if (tid < JPC * BPC) sC[tid] = 0.0f;
    __syncthreads();

    const int w    = tid >> 5;            // warp = k-chunk
    const int lane = tid & 31;
    const int hw   = lane >> 4;           // batch half
    const int lc   = lane & 15;           // owns cols 4lc..4lc+3
    const int k0   = w * KC;
    const int c0   = 4 * lc;

    unsigned long long wreg[2][KC];       // [pair][k]
    {
        const uint32_t wb = smem_u32(sW2 + k0 * SWSTR + c0);
        #pragma unroll
        for (int k = 0; k < KC; k++) {
            asm volatile("ld.shared.u64 %0, [%1];"
                         : "=l"(wreg[0][k]) : "r"(wb + k * (SWSTR * 4)));
            asm volatile("ld.shared.u64 %0, [%1];"
                         : "=l"(wreg[1][k]) : "r"(wb + k * (SWSTR * 4) + 8));
        }
    }
    __syncthreads();   // sW2 dead after this

    const uint32_t hbase  = smem_u32(sH + k0 * BPC + 4 * hw);
    const uint32_t hstore = smem_u32(sH + k0 * BPC) + lane * 16;

    const int lj = tid >> 3;              // epilogue decode (tid<128)
    const int bb = tid & 7;

    for (int s = 0; s < TSTEPS; s++) {
        const int rbuf = s & 1;
        float* sP = sPart + rbuf * (8 * BPC * PSTR);

        // ---- prefetch x_proj gate inputs for epilogue (tid<128)
        float xr[4];
        if (tid < JPC * BPC) {
            const float* xpb = g_xp + ((size_t)((s * 16 + cg) * 8 + bg)) * 512
                             + bb * 64 + lj;
            #pragma unroll
            for (int gate = 0; gate < 4; gate++)
                xr[gate] = __ldg(xpb + gate * 16);
        }

        // ---- poll tagged words of my two producer blocks (data rides along)
        const unsigned long long* pA = &g_hx[rbuf][bg][2 * w][4 * lane];
        const unsigned long long* pB = &g_hx[rbuf][bg][2 * w + 1][4 * lane];
        unsigned long long a0, a1, a2, a3, b0, b1, b2, b3;
        const unsigned exp_tag = (unsigned)s;
        for (;;) {
            a0 = ld_relaxed_u64(pA + 0);
            a1 = ld_relaxed_u64(pA + 1);
            a2 = ld_relaxed_u64(pA + 2);
            a3 = ld_relaxed_u64(pA + 3);
            b0 = ld_relaxed_u64(pB + 0);
            b1 = ld_relaxed_u64(pB + 1);
            b2 = ld_relaxed_u64(pB + 2);
            b3 = ld_relaxed_u64(pB + 3);
            bool ok = (unsigned)(a0 >> 32) == exp_tag &&
                      (unsigned)(a1 >> 32) == exp_tag &&
                      (unsigned)(a2 >> 32) == exp_tag &&
                      (unsigned)(a3 >> 32) == exp_tag &&
                      (unsigned)(b0 >> 32) == exp_tag &&
                      (unsigned)(b1 >> 32) == exp_tag &&
                      (unsigned)(b2 >> 32) == exp_tag &&
                      (unsigned)(b3 >> 32) == exp_tag;
            if (__all_sync(0xffffffffu, ok)) break;
        }
        // ---- unpack h and stage into my private sH rows
        asm volatile("st.shared.v4.f32 [%0], {%1,%2,%3,%4};"
                     :: "r"(hstore),
                        "f"(__uint_as_float((unsigned)a0)),
                        "f"(__uint_as_float((unsigned)a1)),
                        "f"(__uint_as_float((unsigned)a2)),
                        "f"(__uint_as_float((unsigned)a3)));
        asm volatile("st.shared.v4.f32 [%0], {%1,%2,%3,%4};"
                     :: "r"(hstore + 512),
                        "f"(__uint_as_float((unsigned)b0)),
                        "f"(__uint_as_float((unsigned)b1)),
                        "f"(__uint_as_float((unsigned)b2)),
                        "f"(__uint_as_float((unsigned)b3)));
        __syncwarp();

        // ---- GEMM: per k: 1 broadcast LDS.128 + 4 splats + 8 FMA2
        unsigned long long acc[2][4];
        #pragma unroll
        for (int p = 0; p < 2; p++)
            #pragma unroll
            for (int i = 0; i < 4; i++) acc[p][i] = 0ull;

        #pragma unroll
        for (int k = 0; k < KC; k++) {
            float h0, h1, h2f, h3;
            asm volatile("ld.shared.v4.f32 {%0,%1,%2,%3}, [%4];"
                         : "=f"(h0), "=f"(h1), "=f"(h2f), "=f"(h3)
                         : "r"(hbase + k * 32));
            unsigned long long hh[4];
            asm("mov.b64 %0, {%1, %1};" : "=l"(hh[0]) : "f"(h0));
            asm("mov.b64 %0, {%1, %1};" : "=l"(hh[1]) : "f"(h1));
            asm("mov.b64 %0, {%1, %1};" : "=l"(hh[2]) : "f"(h2f));
            asm("mov.b64 %0, {%1, %1};" : "=l"(hh[3]) : "f"(h3));
            #pragma unroll
            for (int i = 0; i < 4; i++) {
                asm volatile("fma.rn.f32x2 %0, %1, %2, %0;"
                             : "+l"(acc[0][i]) : "l"(hh[i]), "l"(wreg[0][k]));
                asm volatile("fma.rn.f32x2 %0, %1, %2, %0;"
                             : "+l"(acc[1][i]) : "l"(hh[i]), "l"(wreg[1][k]));
            }
        }

        // ---- write partials
        #pragma unroll
        for (int i = 0; i < 4; i++) {
            int row = (w * BPC + 4 * hw + i) * PSTR;
            *reinterpret_cast<unsigned long long*>(sP + row + c0)     = acc[0][i];
            *reinterpret_cast<unsigned long long*>(sP + row + c0 + 2) = acc[1][i];
        }
        __syncthreads();

        // ---- epilogue (warps 0-3): reduce, activations, tagged publish
        if (tid < JPC * BPC) {
            float g4[4];
            #pragma unroll
            for (int gate = 0; gate < 4; gate++) {
                int c = gate * JPC + lj;
                float v = xr[gate];
                #pragma unroll
                for (int q = 0; q < 8; q++)
                    v += sP[(q * BPC + bb) * PSTR + c];
                g4[gate] = v;
            }
            float ig = fast_sig(g4[0]);
            float fg = fast_sig(g4[1]);
            float gg = fast_tanh(g4[2]);
            float og = fast_sig(g4[3]);
            float cnew = fg * sC[tid] + ig * gg;
            sC[tid] = cnew;
            float hnew = og * fast_tanh(cnew);

            unsigned long long pk;
            asm("mov.b64 %0, {%1, %2};"
                : "=l"(pk) : "r"(__float_as_uint(hnew)), "r"((unsigned)(s + 1)));
            asm volatile("st.relaxed.gpu.global.u64 [%0], %1;"
                         :: "l"(&g_hx[rbuf ^ 1][bg][cg][tid]), "l"(pk)
                         : "memory");
        }
    }
}

// ---------------------------------------------------------------------------
// final FC: out[b][d] = sum_k h_final[k][b] * fc_w[k][d] + fc_b[d]
// h_2048 (tag 2048) lives in g_hx[0][bg][k>>4][(k&15)*8+bb] low bits
// ---------------------------------------------------------------------------
__global__ void fc_kernel(const float* __restrict__ fc_w,
                          const float* __restrict__ fc_b,
                          float* __restrict__ out) {
    int b = blockIdx.x;
    int d = threadIdx.x;
    int bg = b >> 3, bb = b & 7;
    float acc = fc_b[d];
    #pragma unroll 8
    for (int k = 0; k < HID; k++) {
        unsigned long long v = g_hx[0][bg][k >> 4][(k & 15) * 8 + bb];
        acc += __uint_as_float((unsigned)v) * fc_w[k * DOUT + d];
    }
    out[b * DOUT + d] = acc;
}

// ---------------------------------------------------------------------------
extern "C" void kernel_launch(void* const* d_in, const int* in_sizes, int n_in,
                              void* d_out, int out_size) {
    const float* x    = (const float*)d_in[0];
    const float* W_x  = (const float*)d_in[1];
    const float* W_h  = (const float*)d_in[2];
    const float* bvec = (const float*)d_in[3];
    const float* fc_w = (const float*)d_in[4];
    const float* fc_b = (const float*)d_in[5];
    float* out = (float*)d_out;

    cudaFuncSetAttribute(xproj_kernel,
                         cudaFuncAttributeMaxDynamicSharedMemorySize, XPK_BYTES);
    cudaFuncSetAttribute(lstm_scan_kernel,
                         cudaFuncAttributeMaxDynamicSharedMemorySize, SMEM_BYTES);

    init_kernel<<<(2 * 8 * 16 * JPC * BPC + 255) / 256, 256>>>();
    xproj_kernel<<<dim3(TSTEPS / 16, 8), NTHREADS, XPK_BYTES>>>(x, W_x, bvec);
    lstm_scan_kernel<<<NCTA, NTHREADS, SMEM_BYTES>>>(W_h);
    fc_kernel<<<BATCH, DOUT>>>(fc_w, fc_b, out);
}